// round 4
// baseline (speedup 1.0000x reference)
#include <cuda_runtime.h>
#include <cuda_fp16.h>
#include <math.h>

#define B_  64
#define M_  16
#define A_  128
#define H_  128
#define P_  16
#define NATOM 100
#define NFP   2048
#define NTAB  (NATOM + NFP)     // 2148
#define GRID  128
#define NTHR  512
#define RPB   17                // table rows per block in proj phase

// Scratch (__device__ globals: allocation-free rule)
__device__ __half  g_proj_h[NTAB * H_];     // projected tables, fp16 (1.1MB->0.55MB)
__device__ float   g_mol[B_ * M_ * H_];     // per-molecule mean embeddings
__device__ unsigned g_barrier;              // monotonic grid-barrier counter (zero-init .bss)

// Grid-wide barrier: monotonic counter, safe across graph replays (never reset).
// All GRID=128 blocks are co-resident (grid <= 148 SMs), so spin cannot deadlock.
__device__ __forceinline__ void grid_barrier() {
    __threadfence();               // publish this thread's global writes
    __syncthreads();
    if (threadIdx.x == 0) {
        unsigned old = atomicAdd(&g_barrier, 1u);
        unsigned target = old - (old % GRID) + GRID;
        while (*((volatile unsigned*)&g_barrier) < target) { }
    }
    __syncthreads();
}

__global__ __launch_bounds__(NTHR, 1)
void fused_kernel(const int*   __restrict__ atom_features,
                  const int*   __restrict__ fingerprints,
                  const float* __restrict__ phys,
                  const float* __restrict__ ratios,
                  const float* __restrict__ atom_emb,
                  const float* __restrict__ fp_emb,
                  const float* __restrict__ W_in,
                  const float* __restrict__ b_in,
                  const float* __restrict__ ln_g,
                  const float* __restrict__ ln_b,
                  const float* __restrict__ W1,
                  const float* __restrict__ b1,
                  const float* __restrict__ W2,
                  const float* __restrict__ b2,
                  float* __restrict__ out) {
    const int tid = threadIdx.x;
    const int blk = blockIdx.x;

    // Phase A smem: transposed E tile (stride 20 floats keeps float4 alignment)
    // s_eT is re-used as the gather-index arrays after phase A's compute.
    __shared__ __align__(16) float s_eT[H_ * 20];       // 10.24 KB
    __shared__ float s_p[4 * RPB * H_];                  // 34.8 KB  (K-split partials)
    // head smem
    __shared__ float s_w[M_];
    __shared__ float s_z[H_ + P_];
    __shared__ float s_zn[H_ + P_];
    __shared__ float s_red[8];

    // ---------------- Phase A: projected tables -> g_proj_h (fp16) -----------
    // Blocks 0..5 cover the 100 atom rows (W top half, +b_in);
    // blocks 6..126 cover the 2048 fp rows (W bottom half). Block 127 idles.
    {
        const int h  = tid & 127;
        const int ks = tid >> 7;                 // 0..3 K-slices of 32
        const bool is_atom = (blk < 6);
        const int lrow0 = is_atom ? blk * RPB : (blk - 6) * RPB;   // local row base
        const int nrows = is_atom ? NATOM : NFP;
        const int wbase = is_atom ? 0 : (H_ * H_);

        // Load E tile transposed (zero-fill out-of-range rows)
        for (int i = tid; i < RPB * H_; i += NTHR) {
            int r = i >> 7, d = i & 127;
            int t = lrow0 + r;
            float v = 0.0f;
            if (t < nrows) v = is_atom ? atom_emb[t * H_ + d] : fp_emb[t * H_ + d];
            s_eT[d * 20 + r] = v;
        }
        __syncthreads();

        float acc[RPB];
        #pragma unroll
        for (int r = 0; r < RPB; r++) acc[r] = 0.0f;

        const float* __restrict__ Wp = W_in + wbase + h;
        const int d0 = ks * 32;
        #pragma unroll 8
        for (int dd = 0; dd < 32; dd++) {
            const int d = d0 + dd;
            const float w = Wp[d * H_];
            const float* e = s_eT + d * 20;
            const float4 e0 = *(const float4*)(e);
            const float4 e1 = *(const float4*)(e + 4);
            const float4 e2 = *(const float4*)(e + 8);
            const float4 e3 = *(const float4*)(e + 12);
            const float e16 = e[16];
            acc[0]  += e0.x * w; acc[1]  += e0.y * w; acc[2]  += e0.z * w; acc[3]  += e0.w * w;
            acc[4]  += e1.x * w; acc[5]  += e1.y * w; acc[6]  += e1.z * w; acc[7]  += e1.w * w;
            acc[8]  += e2.x * w; acc[9]  += e2.y * w; acc[10] += e2.z * w; acc[11] += e2.w * w;
            acc[12] += e3.x * w; acc[13] += e3.y * w; acc[14] += e3.z * w; acc[15] += e3.w * w;
            acc[16] += e16 * w;
        }

        #pragma unroll
        for (int r = 0; r < RPB; r++) s_p[(ks * RPB + r) * H_ + h] = acc[r];
        __syncthreads();

        // Reduce K-slices and store fp16
        const int NP = RPB * H_;
        for (int i = tid; i < NP; i += NTHR) {
            int r = i >> 7, hc = i & 127;
            int t = lrow0 + r;
            if (t < nrows) {
                float v = s_p[i] + s_p[NP + i] + s_p[2 * NP + i] + s_p[3 * NP + i];
                if (is_atom) {
                    g_proj_h[t * H_ + hc] = __float2half(v + b_in[hc]);
                } else {
                    g_proj_h[(NATOM + t) * H_ + hc] = __float2half(v);
                }
            }
        }
        __syncthreads();   // done with s_eT; safe to reuse for indices
    }

    // Prefetch gather indices for this block's 8 molecules into smem (pre-barrier:
    // overlaps index load latency with other blocks' proj tails).
    int* s_ia = (int*)s_eT;            // 1024 ints
    int* s_if = ((int*)s_eT) + 1024;   // 1024 ints  (8KB total <= 10.2KB region)
    for (int i = tid; i < 8 * A_; i += NTHR) {
        s_ia[i] = atom_features[blk * 8 * A_ + i] * (H_ / 2);            // half2 row base
        s_if[i] = (NATOM + fingerprints[blk * 8 * A_ + i]) * (H_ / 2);
    }

    grid_barrier();   // g_proj_h complete

    // ---------------- Phase C: per-molecule mean of relu(A+F) ----------------
    // 8 molecules per block; sub = tid>>6 picks the molecule, h2 = tid&63 picks
    // the half2 (pair of embedding dims).
    {
        const __half2* __restrict__ gp2 = (const __half2*)g_proj_h;
        const int sub = tid >> 6;          // 0..7
        const int h2  = tid & 63;          // 0..63
        const int bm  = blk * 8 + sub;
        const int* ia = s_ia + sub * A_;
        const int* ifp = s_if + sub * A_;

        float accx = 0.0f, accy = 0.0f;
        #pragma unroll 4
        for (int a = 0; a < A_; a++) {
            __half2 va = gp2[ia[a] + h2];
            __half2 vf = gp2[ifp[a] + h2];
            float2 fa = __half22float2(va);
            float2 ff = __half22float2(vf);
            accx += fmaxf(fa.x + ff.x, 0.0f);
            accy += fmaxf(fa.y + ff.y, 0.0f);
        }
        float2 res;
        res.x = accx * (1.0f / (float)A_);
        res.y = accy * (1.0f / (float)A_);
        ((float2*)g_mol)[bm * (H_ / 2) + h2] = res;
    }

    grid_barrier();   // g_mol complete

    // ---------------- Phase E: mix + LayerNorm + MLP head (blocks 0..63) -----
    if (blk >= B_) return;
    {
        const int b = blk;
        const int h = tid;    // only tid<128 does work; all 512 hit syncthreads

        if (h < M_) s_w[h] = ratios[b * M_ + h];
        __syncthreads();
        if (h == 0) {
            float s = 0.0f;
            #pragma unroll
            for (int m = 0; m < M_; m++) s += s_w[m];
            float inv = 1.0f / (s + 1e-8f);
            #pragma unroll
            for (int m = 0; m < M_; m++) s_w[m] *= inv;
        }
        __syncthreads();

        if (h < H_) {
            float acc = 0.0f;
            #pragma unroll
            for (int m = 0; m < M_; m++) acc += s_w[m] * g_mol[(b * M_ + m) * H_ + h];
            s_z[h] = acc;
            if (h < P_) {
                float accp = 0.0f;
                #pragma unroll
                for (int m = 0; m < M_; m++) {
                    float v = phys[(b * M_ + m) * P_ + h];
                    if (v != v) v = 0.0f;
                    else if (isinf(v)) v = (v > 0.0f) ? 1000.0f : -1000.0f;
                    accp += s_w[m] * v;
                }
                s_z[H_ + h] = accp;
            }
        }
        __syncthreads();

        if (h < H_) {
            // LayerNorm over 144 elements
            float x  = s_z[h];
            float x2 = x * x;
            if (h < P_) { float e = s_z[H_ + h]; x += e; x2 += e * e; }
            #pragma unroll
            for (int o = 16; o > 0; o >>= 1) {
                x  += __shfl_xor_sync(0xFFFFFFFFu, x,  o);
                x2 += __shfl_xor_sync(0xFFFFFFFFu, x2, o);
            }
            int warp = h >> 5;
            if ((h & 31) == 0) { s_red[warp] = x; s_red[4 + warp] = x2; }
        }
        __syncthreads();

        if (h < H_) {
            float sum  = s_red[0] + s_red[1] + s_red[2] + s_red[3];
            float sum2 = s_red[4] + s_red[5] + s_red[6] + s_red[7];
            const float N = (float)(H_ + P_);
            float mu  = sum / N;
            float var = sum2 / N - mu * mu;
            float rstd = rsqrtf(var + 1e-5f);
            s_zn[h] = (s_z[h] - mu) * rstd * ln_g[h] + ln_b[h];
            if (h < P_) s_zn[H_ + h] = (s_z[H_ + h] - mu) * rstd * ln_g[H_ + h] + ln_b[H_ + h];
        }
        __syncthreads();

        if (h < H_) {
            float t = b1[h];
            #pragma unroll 4
            for (int d = 0; d < H_ + P_; d++) t += s_zn[d] * W1[d * H_ + h];
            float r = fmaxf(t, 0.0f) * W2[h];
            #pragma unroll
            for (int o = 16; o > 0; o >>= 1) r += __shfl_xor_sync(0xFFFFFFFFu, r, o);
            int warp = h >> 5;
            if ((h & 31) == 0) s_red[warp] = r;
        }
        __syncthreads();

        if (h == 0) {
            float y = s_red[0] + s_red[1] + s_red[2] + s_red[3] + b2[0];
            if (y != y) y = 0.0f;
            else if (isinf(y)) y = (y > 0.0f) ? 3.4028234663852886e38f : -3.4028234663852886e38f;
            out[b] = y;
        }
    }
}

extern "C" void kernel_launch(void* const* d_in, const int* in_sizes, int n_in,
                              void* d_out, int out_size) {
    const int*   atom_features = (const int*)  d_in[0];
    const int*   fingerprints  = (const int*)  d_in[1];
    const float* phys          = (const float*)d_in[2];
    const float* ratios        = (const float*)d_in[3];
    const float* atom_emb      = (const float*)d_in[4];
    const float* fp_emb        = (const float*)d_in[5];
    const float* W_in          = (const float*)d_in[6];
    const float* b_in          = (const float*)d_in[7];
    const float* ln_g          = (const float*)d_in[8];
    const float* ln_b          = (const float*)d_in[9];
    const float* W1            = (const float*)d_in[10];
    const float* b1            = (const float*)d_in[11];
    const float* W2            = (const float*)d_in[12];
    const float* b2            = (const float*)d_in[13];
    float* out = (float*)d_out;

    fused_kernel<<<GRID, NTHR>>>(atom_features, fingerprints, phys, ratios,
                                 atom_emb, fp_emb, W_in, b_in, ln_g, ln_b,
                                 W1, b1, W2, b2, out);
}

// round 5
// speedup vs baseline: 1.1691x; 1.1691x over previous
#include <cuda_runtime.h>
#include <cuda_fp16.h>
#include <math.h>

#define B_  64
#define M_  16
#define A_  128
#define H_  128
#define P_  16
#define NATOM 100
#define NFP   2048
#define NTAB  (NATOM + NFP)     // 2148
#define GRID  128
#define NTHR  512
#define RPB   17                // table rows per block in proj phase

// Scratch (__device__ globals: allocation-free rule)
__device__ __half   g_proj_h[NTAB * H_];    // projected tables, fp16 (0.55 MB, L2-resident)
__device__ float    g_mol[B_ * M_ * H_];    // per-molecule mean embeddings
__device__ unsigned g_barrier;              // monotonic grid-barrier counter

// Grid-wide barrier: monotonic counter, safe across graph replays (never reset).
// All GRID=128 blocks are co-resident (grid <= SM count), so spin cannot deadlock.
__device__ __forceinline__ void grid_barrier() {
    __threadfence();
    __syncthreads();
    if (threadIdx.x == 0) {
        unsigned old = atomicAdd(&g_barrier, 1u);
        unsigned target = old - (old % GRID) + GRID;
        while (*((volatile unsigned*)&g_barrier) < target) { }
    }
    __syncthreads();
}

__global__ __launch_bounds__(NTHR, 1)
void fused_kernel(const int*   __restrict__ atom_features,
                  const int*   __restrict__ fingerprints,
                  const float* __restrict__ phys,
                  const float* __restrict__ ratios,
                  const float* __restrict__ atom_emb,
                  const float* __restrict__ fp_emb,
                  const float* __restrict__ W_in,
                  const float* __restrict__ b_in,
                  const float* __restrict__ ln_g,
                  const float* __restrict__ ln_b,
                  const float* __restrict__ W1,
                  const float* __restrict__ b1,
                  const float* __restrict__ W2,
                  const float* __restrict__ b2,
                  float* __restrict__ out) {
    const int tid = threadIdx.x;
    const int blk = blockIdx.x;

    // Aliased smem regions (static, under 48 KB total):
    // region1 (10,240 B): phase A transposed E tile; then gather indices.
    // region2 (34,816 B): phase A K-split partials; then mol partials / head arrays.
    __shared__ __align__(16) float s_r1[2560];
    __shared__ __align__(16) float s_r2[4 * RPB * H_];

    // ---------------- Phase A: projected tables -> g_proj_h (fp16) -----------
    // Blocks 0..5: 100 atom rows (W top half, +b_in). Blocks 6..127: 2048 fp
    // rows (W bottom half). tid = kslice(4) x h(128); each kslice does 32 K-steps.
    {
        float* s_eT = s_r1;                     // [d][r] stride 20
        float* s_p  = s_r2;                     // [ks][r][h]
        const int h  = tid & 127;
        const int ks = tid >> 7;
        const bool is_atom = (blk < 6);
        const int lrow0 = is_atom ? blk * RPB : (blk - 6) * RPB;
        const int nrows = is_atom ? NATOM : NFP;
        const int wbase = is_atom ? 0 : (H_ * H_);

        for (int i = tid; i < RPB * H_; i += NTHR) {
            int r = i >> 7, d = i & 127;
            int t = lrow0 + r;
            float v = 0.0f;
            if (t < nrows) v = is_atom ? atom_emb[t * H_ + d] : fp_emb[t * H_ + d];
            s_eT[d * 20 + r] = v;
        }
        __syncthreads();

        // Prefetch this kslice's 32 W values as one independent LDG batch (MLP=32).
        const float* __restrict__ Wp = W_in + wbase + h;
        const int d0 = ks * 32;
        float wreg[32];
        #pragma unroll
        for (int dd = 0; dd < 32; dd++) wreg[dd] = Wp[(d0 + dd) * H_];

        float acc[RPB];
        #pragma unroll
        for (int r = 0; r < RPB; r++) acc[r] = 0.0f;

        #pragma unroll
        for (int dd = 0; dd < 32; dd++) {
            const float w = wreg[dd];
            const float* e = s_eT + (d0 + dd) * 20;        // broadcast LDS
            const float4 e0 = *(const float4*)(e);
            const float4 e1 = *(const float4*)(e + 4);
            const float4 e2 = *(const float4*)(e + 8);
            const float4 e3 = *(const float4*)(e + 12);
            const float e16 = e[16];
            acc[0]  += e0.x * w; acc[1]  += e0.y * w; acc[2]  += e0.z * w; acc[3]  += e0.w * w;
            acc[4]  += e1.x * w; acc[5]  += e1.y * w; acc[6]  += e1.z * w; acc[7]  += e1.w * w;
            acc[8]  += e2.x * w; acc[9]  += e2.y * w; acc[10] += e2.z * w; acc[11] += e2.w * w;
            acc[12] += e3.x * w; acc[13] += e3.y * w; acc[14] += e3.z * w; acc[15] += e3.w * w;
            acc[16] += e16 * w;
        }

        #pragma unroll
        for (int r = 0; r < RPB; r++) s_p[(ks * RPB + r) * H_ + h] = acc[r];
        __syncthreads();

        const int NP = RPB * H_;
        for (int i = tid; i < NP; i += NTHR) {
            int r = i >> 7, hc = i & 127;
            int t = lrow0 + r;
            if (t < nrows) {
                float v = s_p[i] + s_p[NP + i] + s_p[2 * NP + i] + s_p[3 * NP + i];
                if (is_atom) g_proj_h[t * H_ + hc] = __float2half(v + b_in[hc]);
                else         g_proj_h[(NATOM + t) * H_ + hc] = __float2half(v);
            }
        }
        __syncthreads();   // region1/region2 free for reuse
    }

    // Prefetch gather indices (uint2-row bases) for this block's 8 molecules.
    int* s_ia = (int*)s_r1;            // [8][128]
    int* s_if = ((int*)s_r1) + 1024;   // [8][128]
    for (int i = tid; i < 8 * A_; i += NTHR) {
        s_ia[i] = atom_features[blk * 8 * A_ + i] * (H_ / 4);          // *32 uint2/row
        s_if[i] = (NATOM + fingerprints[blk * 8 * A_ + i]) * (H_ / 4);
    }

    grid_barrier();   // g_proj_h complete everywhere

    // ---------------- Phase C: per-molecule mean of relu(A+F) ----------------
    // One warp reads a whole 256B fp16 row per LDG.64 (uint2/thread).
    // Warp w handles molecule blk*8 + (w>>1), atom range (w&1)*64..+64.
    {
        float* s_part = s_r2;                       // [16][128]
        const uint2* __restrict__ gp = (const uint2*)g_proj_h;
        const int w    = tid >> 5;
        const int lane = tid & 31;
        const int ml   = w >> 1;                    // 0..7 molecule-in-block
        const int a0   = (w & 1) * 64;
        const int* ia  = s_ia + ml * A_ + a0;
        const int* ifp = s_if + ml * A_ + a0;
        const __half2 zero2 = __float2half2_rn(0.0f);

        float4 acc = make_float4(0.0f, 0.0f, 0.0f, 0.0f);
        #pragma unroll 4
        for (int a = 0; a < 64; a++) {
            uint2 ua = gp[ia[a] + lane];
            uint2 uf = gp[ifp[a] + lane];
            __half2 va0 = *(__half2*)&ua.x, va1 = *(__half2*)&ua.y;
            __half2 vf0 = *(__half2*)&uf.x, vf1 = *(__half2*)&uf.y;
            __half2 s0 = __hmax2(__hadd2(va0, vf0), zero2);
            __half2 s1 = __hmax2(__hadd2(va1, vf1), zero2);
            float2 p0 = __half22float2(s0);
            float2 p1 = __half22float2(s1);
            acc.x += p0.x; acc.y += p0.y; acc.z += p1.x; acc.w += p1.y;
        }
        // thread covers dims [4*lane, 4*lane+4)
        s_part[w * H_ + 4 * lane + 0] = acc.x;
        s_part[w * H_ + 4 * lane + 1] = acc.y;
        s_part[w * H_ + 4 * lane + 2] = acc.z;
        s_part[w * H_ + 4 * lane + 3] = acc.w;
        __syncthreads();

        // combine atom-halves, scale, store: 1024 outputs / 512 threads
        #pragma unroll
        for (int i = tid; i < 8 * H_; i += NTHR) {
            int m = i >> 7, d = i & 127;
            float v = (s_part[(2 * m) * H_ + d] + s_part[(2 * m + 1) * H_ + d])
                      * (1.0f / (float)A_);
            g_mol[(blk * 8 + m) * H_ + d] = v;
        }
    }

    grid_barrier();   // g_mol complete everywhere

    // ---------------- Phase E: mix + LayerNorm + MLP head (blocks 0..63) -----
    if (blk >= B_) return;
    {
        float* s_w   = s_r2;          // 16
        float* s_z   = s_r2 + 16;     // 144
        float* s_zn  = s_r2 + 160;    // 144
        float* s_red = s_r2 + 304;    // 8
        const int b = blk;
        const int h = tid;            // tid<128 active; all threads hit syncs

        if (h < M_) s_w[h] = ratios[b * M_ + h];
        __syncthreads();
        if (h == 0) {
            float s = 0.0f;
            #pragma unroll
            for (int m = 0; m < M_; m++) s += s_w[m];
            float inv = 1.0f / (s + 1e-8f);
            #pragma unroll
            for (int m = 0; m < M_; m++) s_w[m] *= inv;
        }
        __syncthreads();

        if (h < H_) {
            float acc = 0.0f;
            #pragma unroll
            for (int m = 0; m < M_; m++) acc += s_w[m] * g_mol[(b * M_ + m) * H_ + h];
            s_z[h] = acc;
            if (h < P_) {
                float accp = 0.0f;
                #pragma unroll
                for (int m = 0; m < M_; m++) {
                    float v = phys[(b * M_ + m) * P_ + h];
                    if (v != v) v = 0.0f;
                    else if (isinf(v)) v = (v > 0.0f) ? 1000.0f : -1000.0f;
                    accp += s_w[m] * v;
                }
                s_z[H_ + h] = accp;
            }
        }
        __syncthreads();

        if (h < H_) {
            float x  = s_z[h];
            float x2 = x * x;
            if (h < P_) { float e = s_z[H_ + h]; x += e; x2 += e * e; }
            #pragma unroll
            for (int o = 16; o > 0; o >>= 1) {
                x  += __shfl_xor_sync(0xFFFFFFFFu, x,  o);
                x2 += __shfl_xor_sync(0xFFFFFFFFu, x2, o);
            }
            int warp = h >> 5;
            if ((h & 31) == 0) { s_red[warp] = x; s_red[4 + warp] = x2; }
        }
        __syncthreads();

        if (h < H_) {
            float sum  = s_red[0] + s_red[1] + s_red[2] + s_red[3];
            float sum2 = s_red[4] + s_red[5] + s_red[6] + s_red[7];
            const float N = (float)(H_ + P_);
            float mu  = sum / N;
            float var = sum2 / N - mu * mu;
            float rstd = rsqrtf(var + 1e-5f);
            s_zn[h] = (s_z[h] - mu) * rstd * ln_g[h] + ln_b[h];
            if (h < P_) s_zn[H_ + h] = (s_z[H_ + h] - mu) * rstd * ln_g[H_ + h] + ln_b[H_ + h];
        }
        __syncthreads();

        if (h < H_) {
            float t = b1[h];
            #pragma unroll 4
            for (int d = 0; d < H_ + P_; d++) t += s_zn[d] * W1[d * H_ + h];
            float r = fmaxf(t, 0.0f) * W2[h];
            #pragma unroll
            for (int o = 16; o > 0; o >>= 1) r += __shfl_xor_sync(0xFFFFFFFFu, r, o);
            int warp = h >> 5;
            if ((h & 31) == 0) s_red[warp] = r;
        }
        __syncthreads();

        if (h == 0) {
            float y = s_red[0] + s_red[1] + s_red[2] + s_red[3] + b2[0];
            if (y != y) y = 0.0f;
            else if (isinf(y)) y = (y > 0.0f) ? 3.4028234663852886e38f : -3.4028234663852886e38f;
            out[b] = y;
        }
    }
}

extern "C" void kernel_launch(void* const* d_in, const int* in_sizes, int n_in,
                              void* d_out, int out_size) {
    const int*   atom_features = (const int*)  d_in[0];
    const int*   fingerprints  = (const int*)  d_in[1];
    const float* phys          = (const float*)d_in[2];
    const float* ratios        = (const float*)d_in[3];
    const float* atom_emb      = (const float*)d_in[4];
    const float* fp_emb        = (const float*)d_in[5];
    const float* W_in          = (const float*)d_in[6];
    const float* b_in          = (const float*)d_in[7];
    const float* ln_g          = (const float*)d_in[8];
    const float* ln_b          = (const float*)d_in[9];
    const float* W1            = (const float*)d_in[10];
    const float* b1            = (const float*)d_in[11];
    const float* W2            = (const float*)d_in[12];
    const float* b2            = (const float*)d_in[13];
    float* out = (float*)d_out;

    fused_kernel<<<GRID, NTHR>>>(atom_features, fingerprints, phys, ratios,
                                 atom_emb, fp_emb, W_in, b_in, ln_g, ln_b,
                                 W1, b1, W2, b2, out);
}

// round 6
// speedup vs baseline: 1.2258x; 1.0485x over previous
#include <cuda_runtime.h>
#include <cuda_fp16.h>
#include <math.h>

#define B_  64
#define M_  16
#define A_  128
#define H_  128
#define P_  16
#define NATOM 100
#define NFP   2048
#define NTAB  (NATOM + NFP)     // 2148
#define GRID  128
#define NTHR  1024
#define RPB   17                // table rows per block in proj phase

// Scratch (__device__ globals: allocation-free rule)
__device__ __half   g_proj_h[NTAB * H_];    // projected tables, fp16 (0.55 MB, L2-resident)
__device__ float    g_mol[B_ * M_ * H_];    // per-molecule mean embeddings
__device__ unsigned g_barrier;              // monotonic grid-barrier counter

// Grid-wide barrier: monotonic counter, safe across graph replays (never reset).
// All GRID=128 blocks are co-resident (grid <= SM count), so spin cannot deadlock.
__device__ __forceinline__ void grid_barrier() {
    __threadfence();
    __syncthreads();
    if (threadIdx.x == 0) {
        unsigned old = atomicAdd(&g_barrier, 1u);
        unsigned target = old - (old % GRID) + GRID;
        while (*((volatile unsigned*)&g_barrier) < target) { }
    }
    __syncthreads();
}

__global__ __launch_bounds__(NTHR, 1)
void fused_kernel(const int*   __restrict__ atom_features,
                  const int*   __restrict__ fingerprints,
                  const float* __restrict__ phys,
                  const float* __restrict__ ratios,
                  const float* __restrict__ atom_emb,
                  const float* __restrict__ fp_emb,
                  const float* __restrict__ W_in,
                  const float* __restrict__ b_in,
                  const float* __restrict__ ln_g,
                  const float* __restrict__ ln_b,
                  const float* __restrict__ W1,
                  const float* __restrict__ b1,
                  const float* __restrict__ W2,
                  const float* __restrict__ b2,
                  float* __restrict__ out) {
    const int tid = threadIdx.x;
    const int blk = blockIdx.x;

    // Aliased smem regions (static, 45 KB total):
    // region1 (10,240 B): phase A transposed E tile; then gather indices.
    // region2 (34,816 B): phase A K-split partials; then mol partials / head arrays.
    __shared__ __align__(16) float s_r1[2560];
    __shared__ __align__(16) float s_r2[4 * RPB * H_];

    // ---------------- Phase A: projected tables -> g_proj_h (fp16) -----------
    // Blocks 0..5: 100 atom rows (W top half, +b_in). Blocks 6..127: 2048 fp
    // rows (W bottom half).
    // Thread layout: h = tid&127 (output col), ks = (tid>>7)&3 (32 K-steps),
    // rh = tid>>9 (row half: rows 0..7 or 8..16).
    {
        float* s_eT = s_r1;                     // [d][r] stride 20 (16B-aligned rows)
        float* s_p  = s_r2;                     // [ks][r][h]
        const int h  = tid & 127;
        const int ks = (tid >> 7) & 3;
        const int rh = tid >> 9;                // 0 or 1
        const int r0 = rh ? 8 : 0;
        const bool is_atom = (blk < 6);
        const int lrow0 = is_atom ? blk * RPB : (blk - 6) * RPB;
        const int nrows = is_atom ? NATOM : NFP;
        const int wbase = is_atom ? 0 : (H_ * H_);

        // Load E tile transposed (zero-fill out-of-range rows): 2176 elems / 1024 thr
        for (int i = tid; i < RPB * H_; i += NTHR) {
            int r = i >> 7, d = i & 127;
            int t = lrow0 + r;
            float v = 0.0f;
            if (t < nrows) v = is_atom ? atom_emb[t * H_ + d] : fp_emb[t * H_ + d];
            s_eT[d * 20 + r] = v;
        }
        __syncthreads();

        const float* __restrict__ Wp = W_in + wbase + h;
        const int d0 = ks * 32;

        float acc[9];
        #pragma unroll
        for (int r = 0; r < 9; r++) acc[r] = 0.0f;

        #pragma unroll
        for (int chunk = 0; chunk < 2; chunk++) {
            // Prefetch 16 W values as one independent LDG batch (MLP=16).
            float wreg[16];
            #pragma unroll
            for (int i = 0; i < 16; i++) wreg[i] = Wp[(d0 + chunk * 16 + i) * H_];

            #pragma unroll
            for (int dd = 0; dd < 16; dd++) {
                const float w = wreg[dd];
                const float* e = s_eT + (d0 + chunk * 16 + dd) * 20 + r0;  // 32B-aligned
                const float4 e0 = *(const float4*)(e);
                const float4 e1 = *(const float4*)(e + 4);
                acc[0] += e0.x * w; acc[1] += e0.y * w; acc[2] += e0.z * w; acc[3] += e0.w * w;
                acc[4] += e1.x * w; acc[5] += e1.y * w; acc[6] += e1.z * w; acc[7] += e1.w * w;
                if (rh) acc[8] += e[8] * w;            // row 16 (only upper half has 9 rows)
            }
        }

        const int nr = rh ? 9 : 8;
        #pragma unroll
        for (int r = 0; r < 9; r++) {
            if (r < nr) s_p[(ks * RPB + r0 + r) * H_ + h] = acc[r];
        }
        __syncthreads();

        // Reduce 4 K-slices, store fp16
        const int NP = RPB * H_;
        for (int i = tid; i < NP; i += NTHR) {
            int r = i >> 7, hc = i & 127;
            int t = lrow0 + r;
            if (t < nrows) {
                float v = s_p[i] + s_p[NP + i] + s_p[2 * NP + i] + s_p[3 * NP + i];
                if (is_atom) g_proj_h[t * H_ + hc] = __float2half(v + b_in[hc]);
                else         g_proj_h[(NATOM + t) * H_ + hc] = __float2half(v);
            }
        }
        __syncthreads();   // regions free for reuse
    }

    // Prefetch gather indices (uint2-row bases) for this block's 8 molecules.
    int* s_ia = (int*)s_r1;            // [8][128]
    int* s_if = ((int*)s_r1) + 1024;   // [8][128]
    for (int i = tid; i < 8 * A_; i += NTHR) {
        s_ia[i] = atom_features[blk * 8 * A_ + i] * (H_ / 4);          // *32 uint2/row
        s_if[i] = (NATOM + fingerprints[blk * 8 * A_ + i]) * (H_ / 4);
    }

    grid_barrier();   // g_proj_h complete everywhere

    // ---------------- Phase C: per-molecule mean of relu(A+F) ----------------
    // One warp reads a whole 256B fp16 row per LDG.64 (uint2/thread).
    // Warp w (0..31): molecule blk*8 + (w>>2), atom quarter (w&3)*32..+32.
    {
        float* s_part = s_r2;                       // [32][128] = 16 KB
        const uint2* __restrict__ gp = (const uint2*)g_proj_h;
        const int w    = tid >> 5;
        const int lane = tid & 31;
        const int ml   = w >> 2;                    // 0..7 molecule-in-block
        const int a0   = (w & 3) * 32;
        const int* ia  = s_ia + ml * A_ + a0;
        const int* ifp = s_if + ml * A_ + a0;
        const __half2 zero2 = __float2half2_rn(0.0f);

        float4 acc = make_float4(0.0f, 0.0f, 0.0f, 0.0f);
        #pragma unroll 8
        for (int a = 0; a < 32; a++) {
            uint2 ua = gp[ia[a] + lane];
            uint2 uf = gp[ifp[a] + lane];
            __half2 va0 = *(__half2*)&ua.x, va1 = *(__half2*)&ua.y;
            __half2 vf0 = *(__half2*)&uf.x, vf1 = *(__half2*)&uf.y;
            __half2 s0 = __hmax2(__hadd2(va0, vf0), zero2);
            __half2 s1 = __hmax2(__hadd2(va1, vf1), zero2);
            float2 p0 = __half22float2(s0);
            float2 p1 = __half22float2(s1);
            acc.x += p0.x; acc.y += p0.y; acc.z += p1.x; acc.w += p1.y;
        }
        // thread covers dims [4*lane, 4*lane+4)
        s_part[w * H_ + 4 * lane + 0] = acc.x;
        s_part[w * H_ + 4 * lane + 1] = acc.y;
        s_part[w * H_ + 4 * lane + 2] = acc.z;
        s_part[w * H_ + 4 * lane + 3] = acc.w;
        __syncthreads();

        // combine 4 atom-quarters, scale, store: 1024 outputs / 1024 threads
        {
            int m = tid >> 7, d = tid & 127;
            float v = (s_part[(4 * m + 0) * H_ + d] + s_part[(4 * m + 1) * H_ + d] +
                       s_part[(4 * m + 2) * H_ + d] + s_part[(4 * m + 3) * H_ + d])
                      * (1.0f / (float)A_);
            g_mol[(blk * 8 + m) * H_ + d] = v;
        }
    }

    grid_barrier();   // g_mol complete everywhere

    // ---------------- Phase E: mix + LayerNorm + MLP head (blocks 0..63) -----
    if (blk >= B_) return;
    {
        float* s_w   = s_r2;          // 16
        float* s_z   = s_r2 + 16;     // 144
        float* s_zn  = s_r2 + 160;    // 144
        float* s_red = s_r2 + 304;    // 8
        const int b = blk;
        const int h = tid;            // tid<128 active; all threads hit syncs

        if (h < M_) s_w[h] = ratios[b * M_ + h];
        __syncthreads();
        if (h == 0) {
            float s = 0.0f;
            #pragma unroll
            for (int m = 0; m < M_; m++) s += s_w[m];
            float inv = 1.0f / (s + 1e-8f);
            #pragma unroll
            for (int m = 0; m < M_; m++) s_w[m] *= inv;
        }
        __syncthreads();

        if (h < H_) {
            float acc = 0.0f;
            #pragma unroll
            for (int m = 0; m < M_; m++) acc += s_w[m] * g_mol[(b * M_ + m) * H_ + h];
            s_z[h] = acc;
            if (h < P_) {
                float accp = 0.0f;
                #pragma unroll
                for (int m = 0; m < M_; m++) {
                    float v = phys[(b * M_ + m) * P_ + h];
                    if (v != v) v = 0.0f;
                    else if (isinf(v)) v = (v > 0.0f) ? 1000.0f : -1000.0f;
                    accp += s_w[m] * v;
                }
                s_z[H_ + h] = accp;
            }
        }
        __syncthreads();

        if (h < H_) {
            float x  = s_z[h];
            float x2 = x * x;
            if (h < P_) { float e = s_z[H_ + h]; x += e; x2 += e * e; }
            #pragma unroll
            for (int o = 16; o > 0; o >>= 1) {
                x  += __shfl_xor_sync(0xFFFFFFFFu, x,  o);
                x2 += __shfl_xor_sync(0xFFFFFFFFu, x2, o);
            }
            int warp = h >> 5;
            if ((h & 31) == 0) { s_red[warp] = x; s_red[4 + warp] = x2; }
        }
        __syncthreads();

        if (h < H_) {
            float sum  = s_red[0] + s_red[1] + s_red[2] + s_red[3];
            float sum2 = s_red[4] + s_red[5] + s_red[6] + s_red[7];
            const float N = (float)(H_ + P_);
            float mu  = sum / N;
            float var = sum2 / N - mu * mu;
            float rstd = rsqrtf(var + 1e-5f);
            s_zn[h] = (s_z[h] - mu) * rstd * ln_g[h] + ln_b[h];
            if (h < P_) s_zn[H_ + h] = (s_z[H_ + h] - mu) * rstd * ln_g[H_ + h] + ln_b[H_ + h];
        }
        __syncthreads();

        if (h < H_) {
            float t = b1[h];
            #pragma unroll 4
            for (int d = 0; d < H_ + P_; d++) t += s_zn[d] * W1[d * H_ + h];
            float r = fmaxf(t, 0.0f) * W2[h];
            #pragma unroll
            for (int o = 16; o > 0; o >>= 1) r += __shfl_xor_sync(0xFFFFFFFFu, r, o);
            int warp = h >> 5;
            if ((h & 31) == 0) s_red[warp] = r;
        }
        __syncthreads();

        if (h == 0) {
            float y = s_red[0] + s_red[1] + s_red[2] + s_red[3] + b2[0];
            if (y != y) y = 0.0f;
            else if (isinf(y)) y = (y > 0.0f) ? 3.4028234663852886e38f : -3.4028234663852886e38f;
            out[b] = y;
        }
    }
}

extern "C" void kernel_launch(void* const* d_in, const int* in_sizes, int n_in,
                              void* d_out, int out_size) {
    const int*   atom_features = (const int*)  d_in[0];
    const int*   fingerprints  = (const int*)  d_in[1];
    const float* phys          = (const float*)d_in[2];
    const float* ratios        = (const float*)d_in[3];
    const float* atom_emb      = (const float*)d_in[4];
    const float* fp_emb        = (const float*)d_in[5];
    const float* W_in          = (const float*)d_in[6];
    const float* b_in          = (const float*)d_in[7];
    const float* ln_g          = (const float*)d_in[8];
    const float* ln_b          = (const float*)d_in[9];
    const float* W1            = (const float*)d_in[10];
    const float* b1            = (const float*)d_in[11];
    const float* W2            = (const float*)d_in[12];
    const float* b2            = (const float*)d_in[13];
    float* out = (float*)d_out;

    fused_kernel<<<GRID, NTHR>>>(atom_features, fingerprints, phys, ratios,
                                 atom_emb, fp_emb, W_in, b_in, ln_g, ln_b,
                                 W1, b1, W2, b2, out);
}